// round 10
// baseline (speedup 1.0000x reference)
#include <cuda_runtime.h>

// 4-D multilinear interpolation on an 8x8x8x8 lattice — 16 lanes per point,
// one lattice corner per lane, one scalar L1-bypassing load per lane.
//
// coordinates: [32768, 4] float32 in [0,1]
// mesh_pred:   [32768, 4096] float32 (each point has its own lattice row)
// out:         [32768] float32
//
// Strides (row-major over mesh dims [8,8,8,8]): dim0=512, dim1=64, dim2=8, dim3=1.
//
// Lane k = tid&15 owns corner (d0,d1,d2,d3) = (k>>3, (k>>2)&1, (k>>1)&1, k&1).
// Corner address = base + d0*512 + d1*64 + d2*8 + d3. The 4 lanes sharing a
// (d0,d1) window touch the same 32B sector -> coalesce into one wavefront.
// __ldcg skips L1 allocation (zero reuse exists). Weight is the product of
// per-dim factors; 4 butterfly shuffles sum the 16 corners.

#define BATCH  32768
#define VOLUME 4096

__global__ __launch_bounds__(256, 8)
void HL_41996190220467_kernel(const float4* __restrict__ coords,
                              const float* __restrict__ mesh,
                              float* __restrict__ out)
{
    int t = blockIdx.x * blockDim.x + threadIdx.x;
    int p = t >> 4;          // point index
    int k = t & 15;          // corner: d0=k>>3, d1=(k>>2)&1, d2=(k>>1)&1, d3=k&1

    float4 c4 = coords[p];   // 16 lanes broadcast-load the same 16B

    float c0 = c4.x * 7.0f;
    float c1 = c4.y * 7.0f;
    float c2 = c4.z * 7.0f;
    float c3 = c4.w * 7.0f;

    int i0 = min(max((int)c0, 0), 6);
    int i1 = min(max((int)c1, 0), 6);
    int i2 = min(max((int)c2, 0), 6);
    int i3 = min(max((int)c3, 0), 6);

    float f0 = c0 - (float)i0;
    float f1 = c1 - (float)i1;
    float f2 = c2 - (float)i2;
    float f3 = c3 - (float)i3;

    int d0 = (k >> 3) & 1, d1 = (k >> 2) & 1, d2 = (k >> 1) & 1, d3 = k & 1;

    // this lane's corner address
    const float* __restrict__ row = mesh + (size_t)p * VOLUME;
    int idx = (i0 + d0) * 512 + (i1 + d1) * 64 + (i2 + d2) * 8 + (i3 + d3);

    // single scalar gather, L2-only (no L1 allocation; data has zero reuse)
    float v = __ldcg(row + idx);

    // corner weight = prod over dims of (d ? f : 1-f)
    float w = (d0 ? f0 : 1.0f - f0)
            * (d1 ? f1 : 1.0f - f1)
            * (d2 ? f2 : 1.0f - f2)
            * (d3 ? f3 : 1.0f - f3);
    float r = v * w;

    // sum the 16 corners of this point
    r += __shfl_xor_sync(0xffffffffu, r, 1);
    r += __shfl_xor_sync(0xffffffffu, r, 2);
    r += __shfl_xor_sync(0xffffffffu, r, 4);
    r += __shfl_xor_sync(0xffffffffu, r, 8);

    if (k == 0) out[p] = r;
}

extern "C" void kernel_launch(void* const* d_in, const int* in_sizes, int n_in,
                              void* d_out, int out_size)
{
    const float4* coords = (const float4*)d_in[0];   // [32768, 4]
    const float*  mesh   = (const float*)d_in[1];    // [32768, 4096]
    float* out = (float*)d_out;                      // [32768]
    (void)in_sizes; (void)n_in; (void)out_size;

    // 32768 points * 16 lanes = 524288 threads = 2048 CTAs of 256
    HL_41996190220467_kernel<<<(BATCH * 16) / 256, 256>>>(coords, mesh, out);
}